// round 2
// baseline (speedup 1.0000x reference)
#include <cuda_runtime.h>
#include <math_constants.h>

#define D      128
#define BGR    512
#define GATES  384   // 3*D
#define NWARP  8
#define NTHR   256

// ---------------- device scratch (no allocation allowed) ----------------
__device__ float g_h[BGR * D];        // hidden state
__device__ float g_gi[BGR * GATES];   // input gates  q_star @ W_ih^T + b_ih
__device__ float g_gh[BGR * GATES];   // hidden gates h @ W_hh^T + b_hh
__device__ int   g_starts[BGR + 1];   // segment boundaries (batch is sorted)

__device__ __forceinline__ float sigf(float v) {
    return 1.f / (1.f + __expf(-v));
}

// batch may be delivered as int32 or int64; sniff layout from a mid element.
// For true int64 sorted batch ids, value at N/4 is in [0, BGR). For int32 data
// reinterpreted as int64, the high 32 bits hold the NEXT sorted id (~128) != 0.
__device__ __forceinline__ bool batch_is_i64(const void* bp, int N) {
    long long v = ((const long long*)bp)[N >> 2];   // byte off <= 2N+8 <= 4N, safe either way
    return (v >= 0 && v < BGR);
}
__device__ __forceinline__ int batch_at(const void* bp, int i, bool is64) {
    int v = is64 ? (int)((const long long*)bp)[i] : ((const int*)bp)[i];
    return min(max(v, 0), BGR - 1);                 // clamp: never index wild
}

// ---------------- segment boundaries from sorted batch ----------------
__global__ void starts_kernel(const void* __restrict__ batch, int N) {
    int i = blockIdx.x * blockDim.x + threadIdx.x;
    if (i >= N) return;
    bool is64 = batch_is_i64(batch, N);
    int bi = batch_at(batch, i, is64);
    if (i == 0) {
        for (int b = 0; b <= bi; b++) g_starts[b] = 0;
    } else {
        int bp = batch_at(batch, i - 1, is64);
        for (int b = bp + 1; b <= bi; b++) g_starts[b] = i;
    }
    if (i == N - 1) {
        for (int b = bi + 1; b <= BGR; b++) g_starts[b] = N;
    }
}

// ---------------- step-1 GRU (h=0, q_star=0 -> gates are biases only) ----------------
__global__ void gru_bias_kernel(const float* __restrict__ b_ih,
                                const float* __restrict__ b_hh,
                                float* __restrict__ q_star) {
    int idx = blockIdx.x * blockDim.x + threadIdx.x;
    if (idx >= BGR * D) return;
    int f = idx & (D - 1);
    int b = idx >> 7;
    float r = sigf(b_ih[f] + b_hh[f]);
    float z = sigf(b_ih[D + f] + b_hh[D + f]);
    float n = tanhf(b_ih[2 * D + f] + r * b_hh[2 * D + f]);
    float h = (1.f - z) * n;   // + z*0
    g_h[idx] = h;
    q_star[b * (2 * D) + f] = h;   // q half of q_star
}

// ---------------- simple tiled sgemm: C[M x G] = A[M x K] @ W[G x K]^T + bias ----------------
// A selected by in_sel (0: external ptr = q_star, 1: g_h), C by out_sel (0: g_gi, 1: g_gh)
__global__ void __launch_bounds__(256) gemm_kernel(const float* __restrict__ A_ext,
                                                   int in_sel,
                                                   const float* __restrict__ W,
                                                   const float* __restrict__ bias,
                                                   int out_sel, int K) {
    const float* __restrict__ A = in_sel ? g_h : A_ext;
    float* __restrict__ C = out_sel ? g_gh : g_gi;

    __shared__ float As[16][64];
    __shared__ float Ws[16][33];

    int m0 = blockIdx.y * 64;
    int g0 = blockIdx.x * 32;
    int t = threadIdx.x;
    int ty = t >> 4;          // 0..15 -> 4 rows each (64 m)
    int tx = t & 15;          // 0..15 -> 2 cols each (32 g)

    float acc[4][2] = {};

    for (int k0 = 0; k0 < K; k0 += 16) {
        // A tile: 64(m) x 16(k); thread: m=t/4, 4 consecutive k
        {
            int m = t >> 2, k = (t & 3) << 2;
            float4 v = *(const float4*)(A + (size_t)(m0 + m) * K + k0 + k);
            As[k][m] = v.x; As[k + 1][m] = v.y; As[k + 2][m] = v.z; As[k + 3][m] = v.w;
        }
        // W tile: 32(g) x 16(k); thread: g=t/8, 2 consecutive k
        {
            int g = t >> 3, k = (t & 7) << 1;
            float2 v = *(const float2*)(W + (size_t)(g0 + g) * K + k0 + k);
            Ws[k][g] = v.x; Ws[k + 1][g] = v.y;
        }
        __syncthreads();
#pragma unroll
        for (int kk = 0; kk < 16; kk++) {
            float a[4], w[2];
#pragma unroll
            for (int i = 0; i < 4; i++) a[i] = As[kk][ty * 4 + i];
            w[0] = Ws[kk][tx * 2];
            w[1] = Ws[kk][tx * 2 + 1];
#pragma unroll
            for (int i = 0; i < 4; i++) {
                acc[i][0] += a[i] * w[0];
                acc[i][1] += a[i] * w[1];
            }
        }
        __syncthreads();
    }
#pragma unroll
    for (int i = 0; i < 4; i++) {
        int m = m0 + ty * 4 + i;
        int g = g0 + tx * 2;
        C[(size_t)m * GATES + g]     = acc[i][0] + bias[g];
        C[(size_t)m * GATES + g + 1] = acc[i][1] + bias[g + 1];
    }
}

// ---------------- GRU gate fusion: h = gru(gi, gh, h); q_star[:, :D] = h ----------------
__global__ void gru_gate_kernel(float* __restrict__ q_star) {
    int idx = blockIdx.x * blockDim.x + threadIdx.x;
    if (idx >= BGR * D) return;
    int f = idx & (D - 1);
    int b = idx >> 7;
    const float* gi = g_gi + (size_t)b * GATES;
    const float* gh = g_gh + (size_t)b * GATES;
    float r = sigf(gi[f] + gh[f]);
    float z = sigf(gi[D + f] + gh[D + f]);
    float n = tanhf(gi[2 * D + f] + r * gh[2 * D + f]);
    float h = (1.f - z) * n + z * g_h[idx];
    g_h[idx] = h;
    q_star[b * (2 * D) + f] = h;
}

// ---------------- fused segment attention (online softmax, one pass over x) ----------------
// block b handles graph b's nodes [starts[b], starts[b+1]); warp per node,
// lane l owns features [4l, 4l+4). Writes r into q_star[:, D:2D].
__global__ void __launch_bounds__(NTHR) attn_kernel(const float* __restrict__ x,
                                                    float* __restrict__ q_star) {
    int b = blockIdx.x;
    int start = g_starts[b];
    int end   = g_starts[b + 1];
    int t = threadIdx.x;
    int warp = t >> 5;
    int lane = t & 31;

    __shared__ __align__(16) float q_s[D];
    __shared__ float wm[NWARP], wsum[NWARP];
    __shared__ __align__(16) float wr[NWARP][D];

    if (t < D) q_s[t] = g_h[(size_t)b * D + t];
    __syncthreads();

    if (start >= end) {                 // empty graph: r = 0
        if (t < D) q_star[(size_t)b * (2 * D) + D + t] = 0.f;
        return;
    }

    float4 qf = *(const float4*)(q_s + lane * 4);
    float m = -CUDART_INF_F;
    float s = 0.f;
    float4 racc = make_float4(0.f, 0.f, 0.f, 0.f);

    for (int i = start + warp; i < end; i += NWARP) {
        float4 xv = *(const float4*)(x + (size_t)i * D + lane * 4);
        float d = xv.x * qf.x + xv.y * qf.y + xv.z * qf.z + xv.w * qf.w;
        d += __shfl_xor_sync(0xffffffffu, d, 16);
        d += __shfl_xor_sync(0xffffffffu, d, 8);
        d += __shfl_xor_sync(0xffffffffu, d, 4);
        d += __shfl_xor_sync(0xffffffffu, d, 2);
        d += __shfl_xor_sync(0xffffffffu, d, 1);
        float mn = fmaxf(m, d);
        float scale = __expf(m - mn);   // 0 on first iter (m=-inf), 1 otherwise unless new max
        float w = __expf(d - mn);
        s = s * scale + w;
        racc.x = racc.x * scale + w * xv.x;
        racc.y = racc.y * scale + w * xv.y;
        racc.z = racc.z * scale + w * xv.z;
        racc.w = racc.w * scale + w * xv.w;
        m = mn;
    }

    if (lane == 0) { wm[warp] = m; wsum[warp] = s; }
    *(float4*)(&wr[warp][lane * 4]) = racc;
    __syncthreads();

    if (t < D) {
        float mb = wm[0];
#pragma unroll
        for (int w = 1; w < NWARP; w++) mb = fmaxf(mb, wm[w]);
        float stot = 0.f, rf = 0.f;
#pragma unroll
        for (int w = 0; w < NWARP; w++) {
            float c = __expf(wm[w] - mb);   // 0 for empty warps (wm=-inf), finite mb
            stot += c * wsum[w];
            rf   += c * wr[w][t];
        }
        q_star[(size_t)b * (2 * D) + D + t] = rf / (stot + 1e-16f);
    }
}

// ---------------- launch ----------------
extern "C" void kernel_launch(void* const* d_in, const int* in_sizes, int n_in,
                              void* d_out, int out_size) {
    const float* x     = (const float*)d_in[0];
    const void*  batch = d_in[1];
    int base = (n_in >= 7) ? 3 : 2;    // d_in[2] may be the batch_size scalar
    const float* W_ih = (const float*)d_in[base];
    const float* W_hh = (const float*)d_in[base + 1];
    const float* b_ih = (const float*)d_in[base + 2];
    const float* b_hh = (const float*)d_in[base + 3];

    float* q_star = (float*)d_out;     // [BGR, 2D] == out_size exactly
    int N = in_sizes[0] / D;

    starts_kernel<<<(N + 255) / 256, 256>>>(batch, N);

    // ---- step 1: GRU collapses to biases (h=0, q_star=0) ----
    gru_bias_kernel<<<(BGR * D + 255) / 256, 256>>>(b_ih, b_hh, q_star);
    attn_kernel<<<BGR, NTHR>>>(x, q_star);

    // ---- steps 2..3 ----
    dim3 ggrid(GATES / 32, BGR / 64);  // 12 x 8 = 96 blocks
    for (int step = 1; step < 3; step++) {
        gemm_kernel<<<ggrid, 256>>>(q_star, 0, W_ih, b_ih, /*out g_gi*/0, 2 * D);
        gemm_kernel<<<ggrid, 256>>>(nullptr, 1, W_hh, b_hh, /*out g_gh*/1, D);
        gru_gate_kernel<<<(BGR * D + 255) / 256, 256>>>(q_star);
        attn_kernel<<<BGR, NTHR>>>(x, q_star);
    }
}

// round 3
// speedup vs baseline: 1.4131x; 1.4131x over previous
#include <cuda_runtime.h>
#include <math_constants.h>

#define D      128
#define BGR    512
#define NWARP  8
#define NTHR   256

// ---------------- device scratch (no allocation allowed) ----------------
__device__ float g_h[2][BGR * D];     // ping-pong hidden state
__device__ int   g_starts[BGR + 1];   // segment boundaries (batch is sorted)

__device__ __forceinline__ float sigf(float v) {
    return 1.f / (1.f + __expf(-v));
}

// batch may be delivered as int32 or int64; sniff layout from a mid element.
__device__ __forceinline__ bool batch_is_i64(const void* bp, int N) {
    long long v = ((const long long*)bp)[N >> 2];
    return (v >= 0 && v < BGR);
}
__device__ __forceinline__ int batch_at(const void* bp, int i, bool is64) {
    int v = is64 ? (int)((const long long*)bp)[i] : ((const int*)bp)[i];
    return min(max(v, 0), BGR - 1);
}

// ---------------- segment boundaries from sorted batch ----------------
__global__ void starts_kernel(const void* __restrict__ batch, int N) {
    int i = blockIdx.x * blockDim.x + threadIdx.x;
    if (i >= N) return;
    bool is64 = batch_is_i64(batch, N);
    int bi = batch_at(batch, i, is64);
    if (i == 0) {
        for (int b = 0; b <= bi; b++) g_starts[b] = 0;
    } else {
        int bp = batch_at(batch, i - 1, is64);
        for (int b = bp + 1; b <= bi; b++) g_starts[b] = i;
    }
    if (i == N - 1) {
        for (int b = bi + 1; b <= BGR; b++) g_starts[b] = N;
    }
}

// ---------------- step-1 GRU (h=0, q_star=0 -> gates are biases only) ----------------
__global__ void gru_bias_kernel(const float* __restrict__ b_ih,
                                const float* __restrict__ b_hh) {
    int idx = blockIdx.x * blockDim.x + threadIdx.x;
    if (idx >= BGR * D) return;
    int f = idx & (D - 1);
    float r = sigf(b_ih[f] + b_hh[f]);
    float z = sigf(b_ih[D + f] + b_hh[D + f]);
    float n = tanhf(b_ih[2 * D + f] + r * b_hh[2 * D + f]);
    g_h[0][idx] = (1.f - z) * n;   // + z*0
}

// ---------------- fused GRU step: gi-GEMM + gh-GEMM + gate nonlinearity ----------------
// C-tile: BT=32 batch rows x FT=16 features. 6 accumulators per output.
// grid = (D/FT=8, BGR/BT=16) = 128 blocks, 256 threads.
// Reads q_star (prev step) and g_h[cur]; writes g_h[nxt] only (no races).
#define BT 32
#define FT 16
#define KT 32
__global__ void __launch_bounds__(NTHR) gru_step_kernel(const float* __restrict__ q_star,
                                                        const float* __restrict__ W_ih,
                                                        const float* __restrict__ W_hh,
                                                        const float* __restrict__ b_ih,
                                                        const float* __restrict__ b_hh,
                                                        int cur) {
    __shared__ float As[KT][BT + 1];
    __shared__ float Wt[3][KT][FT + 1];

    int t  = threadIdx.x;
    int tx = t & 15;          // feature within tile
    int ty = t >> 4;          // 0..15 ; rows ty and ty+16
    int f0 = blockIdx.x * FT;
    int b0 = blockIdx.y * BT;

    float gi_r[2] = {0.f, 0.f}, gi_z[2] = {0.f, 0.f}, gi_n[2] = {0.f, 0.f};
    float gh_r[2] = {0.f, 0.f}, gh_z[2] = {0.f, 0.f}, gh_n[2] = {0.f, 0.f};

    // ---- phase 1: gi += q_star[BTx256] @ W_ih[.,256]^T ----
    {
        const float* A = q_star;
        const int KW = 2 * D;
        for (int k0 = 0; k0 < KW; k0 += KT) {
            {   // A tile: row = t>>3 (32), k = (t&7)*4
                int row = t >> 3, k = (t & 7) << 2;
                float4 v = *(const float4*)(A + (size_t)(b0 + row) * KW + k0 + k);
                As[k][row] = v.x; As[k + 1][row] = v.y; As[k + 2][row] = v.z; As[k + 3][row] = v.w;
            }
            // W tiles: 3 gates x 16 f x 8 k4 = 384 float4 units
            for (int idx = t; idx < 384; idx += NTHR) {
                int g = idx >> 7, rem = idx & 127, f = rem >> 3, k = (rem & 7) << 2;
                float4 v = *(const float4*)(W_ih + (size_t)(g * D + f0 + f) * KW + k0 + k);
                Wt[g][k][f] = v.x; Wt[g][k + 1][f] = v.y; Wt[g][k + 2][f] = v.z; Wt[g][k + 3][f] = v.w;
            }
            __syncthreads();
#pragma unroll
            for (int kk = 0; kk < KT; kk++) {
                float a0 = As[kk][ty], a1 = As[kk][ty + 16];
                float wr = Wt[0][kk][tx], wz = Wt[1][kk][tx], wn = Wt[2][kk][tx];
                gi_r[0] += a0 * wr; gi_z[0] += a0 * wz; gi_n[0] += a0 * wn;
                gi_r[1] += a1 * wr; gi_z[1] += a1 * wz; gi_n[1] += a1 * wn;
            }
            __syncthreads();
        }
    }
    // ---- phase 2: gh += h[BTx128] @ W_hh[.,128]^T ----
    {
        const float* A = g_h[cur];
        const int KW = D;
        for (int k0 = 0; k0 < KW; k0 += KT) {
            {
                int row = t >> 3, k = (t & 7) << 2;
                float4 v = *(const float4*)(A + (size_t)(b0 + row) * KW + k0 + k);
                As[k][row] = v.x; As[k + 1][row] = v.y; As[k + 2][row] = v.z; As[k + 3][row] = v.w;
            }
            for (int idx = t; idx < 384; idx += NTHR) {
                int g = idx >> 7, rem = idx & 127, f = rem >> 3, k = (rem & 7) << 2;
                float4 v = *(const float4*)(W_hh + (size_t)(g * D + f0 + f) * KW + k0 + k);
                Wt[g][k][f] = v.x; Wt[g][k + 1][f] = v.y; Wt[g][k + 2][f] = v.z; Wt[g][k + 3][f] = v.w;
            }
            __syncthreads();
#pragma unroll
            for (int kk = 0; kk < KT; kk++) {
                float a0 = As[kk][ty], a1 = As[kk][ty + 16];
                float wr = Wt[0][kk][tx], wz = Wt[1][kk][tx], wn = Wt[2][kk][tx];
                gh_r[0] += a0 * wr; gh_z[0] += a0 * wz; gh_n[0] += a0 * wn;
                gh_r[1] += a1 * wr; gh_z[1] += a1 * wz; gh_n[1] += a1 * wn;
            }
            __syncthreads();
        }
    }

    // ---- epilogue: GRU gates, write new h ----
    int f = f0 + tx;
    float bir = b_ih[f],       bhr = b_hh[f];
    float biz = b_ih[D + f],   bhz = b_hh[D + f];
    float bin_ = b_ih[2 * D + f], bhn = b_hh[2 * D + f];
#pragma unroll
    for (int rr = 0; rr < 2; rr++) {
        int row = b0 + ty + rr * 16;
        float hold = g_h[cur][(size_t)row * D + f];
        float r = sigf(gi_r[rr] + bir + gh_r[rr] + bhr);
        float z = sigf(gi_z[rr] + biz + gh_z[rr] + bhz);
        float n = tanhf(gi_n[rr] + bin_ + r * (gh_n[rr] + bhn));
        g_h[cur ^ 1][(size_t)row * D + f] = (1.f - z) * n + z * hold;
    }
}

// ---------------- fused segment attention (online softmax, one pass over x) ----------------
// block b handles graph b; warp per 4 contiguous nodes; lane l owns features [4l,4l+4).
// Writes BOTH halves of q_star: [:, :D] = h, [:, D:] = r.
__global__ void __launch_bounds__(NTHR) attn_kernel(const float* __restrict__ x,
                                                    const float* __restrict__ h,
                                                    float* __restrict__ q_star) {
    int b = blockIdx.x;
    int start = g_starts[b];
    int end   = g_starts[b + 1];
    int t = threadIdx.x;
    int warp = t >> 5;
    int lane = t & 31;

    __shared__ __align__(16) float q_s[D];
    __shared__ float wm[NWARP], wsum[NWARP];
    __shared__ __align__(16) float wr[NWARP][D];

    if (t < D) q_s[t] = h[(size_t)b * D + t];
    __syncthreads();

    if (t < D) q_star[(size_t)b * (2 * D) + t] = q_s[t];   // q half (always)

    if (start >= end) {                 // empty graph: r = 0
        if (t < D) q_star[(size_t)b * (2 * D) + D + t] = 0.f;
        return;
    }

    float4 qf = *(const float4*)(q_s + lane * 4);
    float m = -CUDART_INF_F;
    float s = 0.f;
    float4 racc = make_float4(0.f, 0.f, 0.f, 0.f);

    for (int base = start + warp * 4; base < end; base += NWARP * 4) {
        float4 xv[4];
        float  d[4];
#pragma unroll
        for (int j = 0; j < 4; j++) {
            int i = base + j;
            if (i < end) {
                xv[j] = *(const float4*)(x + (size_t)i * D + lane * 4);
                d[j] = xv[j].x * qf.x + xv[j].y * qf.y + xv[j].z * qf.z + xv[j].w * qf.w;
            } else {
                xv[j] = make_float4(0.f, 0.f, 0.f, 0.f);
                d[j] = -CUDART_INF_F;
            }
        }
#pragma unroll
        for (int off = 16; off >= 1; off >>= 1) {
#pragma unroll
            for (int j = 0; j < 4; j++) d[j] += __shfl_xor_sync(0xffffffffu, d[j], off);
        }
#pragma unroll
        for (int j = 0; j < 4; j++) {
            if (d[j] <= m) {                       // common path: max unchanged (warp-uniform)
                float w = __expf(d[j] - m);        // 0 for OOB (-inf)
                s += w;
                racc.x += w * xv[j].x; racc.y += w * xv[j].y;
                racc.z += w * xv[j].z; racc.w += w * xv[j].w;
            } else {                               // new max: rescale
                float sc = __expf(m - d[j]);       // 0 on first node (m=-inf)
                m = d[j];
                s = s * sc + 1.f;
                racc.x = racc.x * sc + xv[j].x; racc.y = racc.y * sc + xv[j].y;
                racc.z = racc.z * sc + xv[j].z; racc.w = racc.w * sc + xv[j].w;
            }
        }
    }

    if (lane == 0) { wm[warp] = m; wsum[warp] = s; }
    *(float4*)(&wr[warp][lane * 4]) = racc;
    __syncthreads();

    if (t < D) {
        float mb = wm[0];
#pragma unroll
        for (int w = 1; w < NWARP; w++) mb = fmaxf(mb, wm[w]);
        float stot = 0.f, rf = 0.f;
#pragma unroll
        for (int w = 0; w < NWARP; w++) {
            float c = __expf(wm[w] - mb);   // 0 for empty warps (wm=-inf)
            stot += c * wsum[w];
            rf   += c * wr[w][t];
        }
        q_star[(size_t)b * (2 * D) + D + t] = rf / (stot + 1e-16f);
    }
}

// ---------------- launch ----------------
extern "C" void kernel_launch(void* const* d_in, const int* in_sizes, int n_in,
                              void* d_out, int out_size) {
    const float* x     = (const float*)d_in[0];
    const void*  batch = d_in[1];
    int base = (n_in >= 7) ? 3 : 2;    // d_in[2] may be the batch_size scalar
    const float* W_ih = (const float*)d_in[base];
    const float* W_hh = (const float*)d_in[base + 1];
    const float* b_ih = (const float*)d_in[base + 2];
    const float* b_hh = (const float*)d_in[base + 3];

    float* q_star = (float*)d_out;     // [BGR, 2D]
    int N = in_sizes[0] / D;

    // device-symbol addresses for attn's h argument
    float* h_base;
    cudaGetSymbolAddress((void**)&h_base, g_h);

    starts_kernel<<<(N + 255) / 256, 256>>>(batch, N);

    // ---- step 1: GRU collapses to biases (h=0, q_star=0) -> g_h[0] ----
    gru_bias_kernel<<<(BGR * D + 255) / 256, 256>>>(b_ih, b_hh);
    attn_kernel<<<BGR, NTHR>>>(x, h_base, q_star);

    // ---- steps 2..3 ----
    dim3 ggrid(D / FT, BGR / BT);      // 8 x 16 = 128 blocks
    gru_step_kernel<<<ggrid, NTHR>>>(q_star, W_ih, W_hh, b_ih, b_hh, 0);   // -> g_h[1]
    attn_kernel<<<BGR, NTHR>>>(x, h_base + BGR * D, q_star);

    gru_step_kernel<<<ggrid, NTHR>>>(q_star, W_ih, W_hh, b_ih, b_hh, 1);   // -> g_h[0]
    attn_kernel<<<BGR, NTHR>>>(x, h_base, q_star);
}

// round 4
// speedup vs baseline: 1.6994x; 1.2026x over previous
#include <cuda_runtime.h>
#include <math_constants.h>

#define D      128
#define BGR    512
#define NWARP  8
#define NTHR   256
#define KW     256          // GEMM K (= 2*D)
#define GCOLS  512          // GEMM output cols (4 gates x 128 features, interleaved)

// ---------------- device scratch (no allocation allowed) ----------------
__device__ float g_h[BGR * D];            // hidden state (current)
__device__ float g_Wbig[GCOLS * KW];      // merged weights, col 4f+g, k over q_star
__device__ float g_bias[GCOLS];           // merged biases [br,bz,bin,bhn] per feature
__device__ int   g_starts[BGR + 1];       // segment boundaries (batch is sorted)

__device__ __forceinline__ float sigf(float v) {
    return 1.f / (1.f + __expf(-v));
}

// batch may be delivered as int32 or int64; sniff layout from a mid element.
__device__ __forceinline__ bool batch_is_i64(const void* bp, int N) {
    long long v = ((const long long*)bp)[N >> 2];
    return (v >= 0 && v < BGR);
}
__device__ __forceinline__ int batch_at(const void* bp, int i, bool is64) {
    int v = is64 ? (int)((const long long*)bp)[i] : ((const int*)bp)[i];
    return min(max(v, 0), BGR - 1);
}

// ---------------- segment boundaries from sorted batch ----------------
__global__ void starts_kernel(const void* __restrict__ batch, int N) {
    int i = blockIdx.x * blockDim.x + threadIdx.x;
    if (i >= N) return;
    bool is64 = batch_is_i64(batch, N);
    int bi = batch_at(batch, i, is64);
    if (i == 0) {
        for (int b = 0; b <= bi; b++) g_starts[b] = 0;
    } else {
        int bp = batch_at(batch, i - 1, is64);
        for (int b = bp + 1; b <= bi; b++) g_starts[b] = i;
    }
    if (i == N - 1) {
        for (int b = bi + 1; b <= BGR; b++) g_starts[b] = N;
    }
}

// ---------------- weight/bias merge (once per launch; weights step-invariant) ----------------
// col c = 4f+g:  g=0: r-sum weights, g=1: z-sum, g=2: gi_n, g=3: gh_n (zero-padded k>=128)
__global__ void prep_kernel(const float* __restrict__ W_ih, const float* __restrict__ W_hh,
                            const float* __restrict__ b_ih, const float* __restrict__ b_hh) {
    int idx = blockIdx.x * blockDim.x + threadIdx.x;   // over GCOLS*KW
    if (idx >= GCOLS * KW) return;
    int c = idx >> 8;          // 0..511
    int k = idx & (KW - 1);
    int f = c >> 2, g = c & 3;
    float v;
    if (g == 0)      v = W_ih[(size_t)f * KW + k]         + (k < D ? W_hh[(size_t)f * D + k] : 0.f);
    else if (g == 1) v = W_ih[(size_t)(D + f) * KW + k]   + (k < D ? W_hh[(size_t)(D + f) * D + k] : 0.f);
    else if (g == 2) v = W_ih[(size_t)(2 * D + f) * KW + k];
    else             v = (k < D) ? W_hh[(size_t)(2 * D + f) * D + k] : 0.f;
    g_Wbig[(size_t)c * KW + k] = v;
    if (k == 0) {
        float b;
        if (g == 0)      b = b_ih[f] + b_hh[f];
        else if (g == 1) b = b_ih[D + f] + b_hh[D + f];
        else if (g == 2) b = b_ih[2 * D + f];
        else             b = b_hh[2 * D + f];
        g_bias[c] = b;
    }
}

// ---------------- step-1 GRU (h=0, q_star=0 -> gates are biases only) ----------------
__global__ void gru_bias_kernel(const float* __restrict__ b_ih,
                                const float* __restrict__ b_hh) {
    int idx = blockIdx.x * blockDim.x + threadIdx.x;
    if (idx >= BGR * D) return;
    int f = idx & (D - 1);
    float r = sigf(b_ih[f] + b_hh[f]);
    float z = sigf(b_ih[D + f] + b_hh[D + f]);
    float n = tanhf(b_ih[2 * D + f] + r * b_hh[2 * D + f]);
    g_h[idx] = (1.f - z) * n;   // + z*0
}

// ---------------- whole GRU step as ONE register-tiled GEMM with gate epilogue ----------
// C[512 x 512] = q_star[512 x 256] @ Wbig^T ; block tile 32 rows x 64 cols (16 features),
// 128 threads, thread tile 4x4 (its 4 cols = one feature's [r,z,gin,ghn]).
// Epilogue computes h_new and writes g_h. h_old = q_star[:, :D].
#define GKT 16
__global__ void __launch_bounds__(128) gru_fused_kernel(const float* __restrict__ q_star) {
    __shared__ __align__(16) float As[GKT][32];
    __shared__ __align__(16) float Ws[GKT][64];

    int t  = threadIdx.x;
    int tx = t & 15;           // feature within tile
    int ty = t >> 4;           // 0..7 -> 4 rows each
    int r0 = blockIdx.y * 32;
    int c0 = blockIdx.x * 64;

    float acc[4][4] = {};

    for (int k0 = 0; k0 < KW; k0 += GKT) {
        {   // A tile 32r x 16k: thread row=t>>2, k=(t&3)*4 (coalesced 64B/row)
            int row = t >> 2, k = (t & 3) << 2;
            float4 v = *(const float4*)(q_star + (size_t)(r0 + row) * KW + k0 + k);
            As[k][row] = v.x; As[k + 1][row] = v.y; As[k + 2][row] = v.z; As[k + 3][row] = v.w;
        }
        {   // W tile 64c x 16k: thread col=t>>1, k=(t&1)*8 (two float4)
            int col = t >> 1, k = (t & 1) << 3;
            const float* wp = g_Wbig + (size_t)(c0 + col) * KW + k0 + k;
            float4 v0 = *(const float4*)wp;
            float4 v1 = *(const float4*)(wp + 4);
            Ws[k][col]     = v0.x; Ws[k + 1][col] = v0.y; Ws[k + 2][col] = v0.z; Ws[k + 3][col] = v0.w;
            Ws[k + 4][col] = v1.x; Ws[k + 5][col] = v1.y; Ws[k + 6][col] = v1.z; Ws[k + 7][col] = v1.w;
        }
        __syncthreads();
#pragma unroll
        for (int kk = 0; kk < GKT; kk++) {
            float a[4], w[4];
            *(float4*)a = *(const float4*)&As[kk][ty * 4];
            *(float4*)w = *(const float4*)&Ws[kk][tx * 4];
#pragma unroll
            for (int i = 0; i < 4; i++) {
#pragma unroll
                for (int j = 0; j < 4; j++) acc[i][j] += a[i] * w[j];
            }
        }
        __syncthreads();
    }

    // ---- GRU gate epilogue ----
    int f = (c0 >> 2) + tx;                       // global feature id
    float4 gb = *(const float4*)&g_bias[4 * f];   // [br, bz, bin, bhn]
#pragma unroll
    for (int i = 0; i < 4; i++) {
        int row = r0 + ty * 4 + i;
        float hold = q_star[(size_t)row * KW + f];    // h_old = q half of q_star
        float r = sigf(acc[i][0] + gb.x);
        float z = sigf(acc[i][1] + gb.y);
        float n = tanhf(acc[i][2] + gb.z + r * (acc[i][3] + gb.w));
        g_h[(size_t)row * D + f] = (1.f - z) * n + z * hold;
    }
}

// ---------------- fused segment attention (online softmax, one pass over x) ----------------
// block b handles graph b; warp per 4 contiguous nodes; lane l owns features [4l,4l+4).
// Writes BOTH halves of q_star: [:, :D] = h, [:, D:] = r.
__global__ void __launch_bounds__(NTHR) attn_kernel(const float* __restrict__ x,
                                                    float* __restrict__ q_star) {
    int b = blockIdx.x;
    int start = g_starts[b];
    int end   = g_starts[b + 1];
    int t = threadIdx.x;
    int warp = t >> 5;
    int lane = t & 31;

    __shared__ __align__(16) float q_s[D];
    __shared__ float wm[NWARP], wsum[NWARP];
    __shared__ __align__(16) float wr[NWARP][D];

    if (t < D) q_s[t] = g_h[(size_t)b * D + t];
    __syncthreads();

    if (t < D) q_star[(size_t)b * (2 * D) + t] = q_s[t];   // q half (always)

    if (start >= end) {                 // empty graph: r = 0
        if (t < D) q_star[(size_t)b * (2 * D) + D + t] = 0.f;
        return;
    }

    float4 qf = *(const float4*)(q_s + lane * 4);
    float m = -CUDART_INF_F;
    float s = 0.f;
    float4 racc = make_float4(0.f, 0.f, 0.f, 0.f);

    for (int base = start + warp * 4; base < end; base += NWARP * 4) {
        float4 xv[4];
        float  d[4];
#pragma unroll
        for (int j = 0; j < 4; j++) {
            int i = base + j;
            if (i < end) {
                xv[j] = *(const float4*)(x + (size_t)i * D + lane * 4);
                d[j] = xv[j].x * qf.x + xv[j].y * qf.y + xv[j].z * qf.z + xv[j].w * qf.w;
            } else {
                xv[j] = make_float4(0.f, 0.f, 0.f, 0.f);
                d[j] = -CUDART_INF_F;
            }
        }
#pragma unroll
        for (int off = 16; off >= 1; off >>= 1) {
#pragma unroll
            for (int j = 0; j < 4; j++) d[j] += __shfl_xor_sync(0xffffffffu, d[j], off);
        }
#pragma unroll
        for (int j = 0; j < 4; j++) {
            if (d[j] <= m) {                       // common path: max unchanged (warp-uniform)
                float w = __expf(d[j] - m);        // 0 for OOB (-inf)
                s += w;
                racc.x += w * xv[j].x; racc.y += w * xv[j].y;
                racc.z += w * xv[j].z; racc.w += w * xv[j].w;
            } else {                               // new max: rescale
                float sc = __expf(m - d[j]);       // 0 on first node (m=-inf)
                m = d[j];
                s = s * sc + 1.f;
                racc.x = racc.x * sc + xv[j].x; racc.y = racc.y * sc + xv[j].y;
                racc.z = racc.z * sc + xv[j].z; racc.w = racc.w * sc + xv[j].w;
            }
        }
    }

    if (lane == 0) { wm[warp] = m; wsum[warp] = s; }
    *(float4*)(&wr[warp][lane * 4]) = racc;
    __syncthreads();

    if (t < D) {
        float mb = wm[0];
#pragma unroll
        for (int w = 1; w < NWARP; w++) mb = fmaxf(mb, wm[w]);
        float stot = 0.f, rf = 0.f;
#pragma unroll
        for (int w = 0; w < NWARP; w++) {
            float c = __expf(wm[w] - mb);   // 0 for empty warps (wm=-inf)
            stot += c * wsum[w];
            rf   += c * wr[w][t];
        }
        q_star[(size_t)b * (2 * D) + D + t] = rf / (stot + 1e-16f);
    }
}

// ---------------- launch ----------------
extern "C" void kernel_launch(void* const* d_in, const int* in_sizes, int n_in,
                              void* d_out, int out_size) {
    const float* x     = (const float*)d_in[0];
    const void*  batch = d_in[1];
    int base = (n_in >= 7) ? 3 : 2;    // d_in[2] may be the batch_size scalar
    const float* W_ih = (const float*)d_in[base];
    const float* W_hh = (const float*)d_in[base + 1];
    const float* b_ih = (const float*)d_in[base + 2];
    const float* b_hh = (const float*)d_in[base + 3];

    float* q_star = (float*)d_out;     // [BGR, 2D]
    int N = in_sizes[0] / D;

    starts_kernel<<<(N + 255) / 256, 256>>>(batch, N);
    prep_kernel<<<(GCOLS * KW + 255) / 256, 256>>>(W_ih, W_hh, b_ih, b_hh);

    // ---- step 1: GRU collapses to biases (h=0, q_star=0) -> g_h ----
    gru_bias_kernel<<<(BGR * D + 255) / 256, 256>>>(b_ih, b_hh);
    attn_kernel<<<BGR, NTHR>>>(x, q_star);

    // ---- steps 2..3: one fused GEMM+gates kernel per step ----
    dim3 ggrid(GCOLS / 64, BGR / 32);  // 8 x 16 = 128 blocks
    gru_fused_kernel<<<ggrid, 128>>>(q_star);
    attn_kernel<<<BGR, NTHR>>>(x, q_star);

    gru_fused_kernel<<<ggrid, 128>>>(q_star);
    attn_kernel<<<BGR, NTHR>>>(x, q_star);
}